// round 6
// baseline (speedup 1.0000x reference)
#include <cuda_runtime.h>
#include <math.h>

#define LOG2PI_F 1.83787706640934548356f
#define MS 72   // M row stride (floats): 16B-aligned rows
#define WS 68   // W row stride (floats): 16B-aligned rows

// ---------------- device-global scratch (no allocations allowed) ----------------
__device__ __align__(16) float g_Saa[64 * 64];
__device__ __align__(16) float g_Sab[64 * 64];
__device__ __align__(16) float g_Sbb[64 * 64];
__device__ float g_fmu[64];
__device__ float g_fvar[64 * 64];
__device__ float g_fscore;

// ---------------- prep: trans_var = C^T C, split into blocks ----------------
__global__ void prep_kernel(const float* __restrict__ C) {
    int idx = blockIdx.x * blockDim.x + threadIdx.x;
    if (idx >= 128 * 128) return;
    int i = idx >> 7, j = idx & 127;
    float s = 0.f;
#pragma unroll 8
    for (int k = 0; k < 128; k++) s += C[k * 128 + i] * C[k * 128 + j];
    if (i < 64) {
        if (j < 64) g_Saa[i * 64 + j] = s;
        else        g_Sab[i * 64 + (j - 64)] = s;
    } else if (j >= 64) {
        g_Sbb[(i - 64) * 64 + (j - 64)] = s;
    }
}

// ---- factor an 8x8 SPD block held row-wise in lanes 0..7 regs; produce Linv ----
// d[] on entry: row r of the block. Writes Li (8x8 Linv), ldiag[kb+r]=L_rr,
// idg[kb+r]=1/L_rr. Never writes the block back to M (nothing reads it).
__device__ __forceinline__ void factor8_lane(float d[8], int r, int kb,
                                             float* Li, float* ldiag, float* idg) {
    float myrp = 0.f;
#pragma unroll
    for (int c = 0; c < 8; c++) {
        float piv = __shfl_sync(0xffu, d[c], c);
        float rp = rsqrtf(piv);
        float l = d[c] * rp;        // lane >= c: L[r][c]
        d[c] = l;
        if (c == r) myrp = rp;
#pragma unroll
        for (int cc = c + 1; cc < 8; cc++)
            d[cc] -= l * __shfl_sync(0xffu, l, cc);
    }
    ldiag[kb + r] = d[r];
    idg[kb + r] = myrp;
    // invert L (lower 8x8) by forward substitution, row-by-row across lanes
    float li[8], s[8];
#pragma unroll
    for (int c = 0; c < 8; c++) { li[c] = 0.f; s[c] = 0.f; }
#pragma unroll
    for (int rr = 0; rr < 8; rr++) {
        if (r == rr) {
#pragma unroll
            for (int c = 0; c < 8; c++)
                li[c] = (c == rr) ? myrp : -myrp * s[c];
        }
#pragma unroll
        for (int c = 0; c < 8; c++) {
            float b = __shfl_sync(0xffu, li[c], rr);
            if (r > rr) s[c] += d[rr] * b;
        }
    }
#pragma unroll
    for (int c = 0; c < 8; c++) Li[r * 8 + c] = li[c];
}

// ---------------- blocked Cholesky (rank-8) + forward substitution ----------------
// Semantics identical to R4: M panel cols hold L (scaled), W becomes Z = L^-1 W.
// Diag factorization of block b+1 runs DURING phase 3 of block b (warp0 lanes 0-7),
// with the 8x8 inverse computed there too; phase 2 is dense matvecs against Linv.
// 16 __syncthreads per factorization.
template <bool TRI>
__device__ __forceinline__ void chol64b(float* M, float* W, float* Li,
                                        float* ldiag, float* idg, int tid) {
    // initial factor of block 0
    if (tid < 8) {
        float d[8];
        *(float4*)&d[0] = *(const float4*)&M[tid * MS + 0];
        *(float4*)&d[4] = *(const float4*)&M[tid * MS + 4];
        factor8_lane(d, tid, 0, Li, ldiag, idg);
    }
    __syncthreads();
#pragma unroll 1
    for (int b = 0; b < 8; b++) {
        const int kb = b << 3;
        const int ni = 56 - kb;
        const int ncols = TRI ? (kb + 9) : 65;
        // ---- phase 2: panel rows (tid<ni) and W cols (tid 128..) via Linv matvec ----
        if (tid < ni) {
            const int i = kb + 8 + tid;
            float p[8], o[8];
            *(float4*)&p[0] = *(const float4*)&M[i * MS + kb];
            *(float4*)&p[4] = *(const float4*)&M[i * MS + kb + 4];
#pragma unroll
            for (int c = 0; c < 8; c++) {
                float acc = 0.f;
#pragma unroll
                for (int d2 = 0; d2 <= c; d2++) acc += Li[c * 8 + d2] * p[d2];
                o[c] = acc;
            }
            *(float4*)&M[i * MS + kb]     = make_float4(o[0], o[1], o[2], o[3]);
            *(float4*)&M[i * MS + kb + 4] = make_float4(o[4], o[5], o[6], o[7]);
        } else if (tid >= 128 && tid < 128 + ncols) {
            const int q = tid - 128;
            const int j = (q == ncols - 1) ? 64 : q;
            float w[8], o[8];
#pragma unroll
            for (int c = 0; c < 8; c++) w[c] = W[(kb + c) * WS + j];
#pragma unroll
            for (int c = 0; c < 8; c++) {
                float acc = 0.f;
#pragma unroll
                for (int d2 = 0; d2 <= c; d2++) acc += Li[c * 8 + d2] * w[d2];
                o[c] = acc;
            }
#pragma unroll
            for (int c = 0; c < 8; c++) W[(kb + c) * WS + j] = o[c];
        }
        __syncthreads();
        // ---- phase 3: trailing update; warp0 lanes 0-7 also prep+factor next diag ----
        if (b < 7) {
            if (tid < 8) {
                const int i = kb + 8 + tid;
                float a[8], d[8];
                *(float4*)&a[0] = *(const float4*)&M[i * MS + kb];
                *(float4*)&a[4] = *(const float4*)&M[i * MS + kb + 4];
                *(float4*)&d[0] = *(const float4*)&M[i * MS + kb + 8];
                *(float4*)&d[4] = *(const float4*)&M[i * MS + kb + 12];
#pragma unroll
                for (int m = 0; m < 8; m++) {
                    float am = a[m];
#pragma unroll
                    for (int c = 0; c < 8; c++)
                        d[c] -= am * __shfl_sync(0xffu, a[m], c);
                }
                factor8_lane(d, tid, kb + 8, Li, ldiag, idg);
            } else {
                const int mt = (56 - kb) >> 2;
                const int nMtG = ((mt * (mt + 1)) >> 1) - 3;     // skip 3 next-diag tiles
                const int nreg = TRI ? (kb + 8) : 64;
                const int wct = nreg >> 2;
                const int nWt = mt * wct;
                const int total = 2 * nMtG + 2 * nWt + mt;
                for (int u = tid - 8; u < total; u += 248) {
                    if (u < 2 * nMtG) {
                        int t4 = (u >> 1) + 3, half = u & 1;
                        float xf = 8.f * (float)t4 + 1.f;
                        int ti = (int)((xf * rsqrtf(xf) - 1.f) * 0.5f);
                        while ((ti + 1) * (ti + 2) / 2 <= t4) ++ti;
                        while (ti * (ti + 1) / 2 > t4) --ti;
                        int tj = t4 - ((ti * (ti + 1)) >> 1);
                        int i0 = kb + 8 + (ti << 2) + (half << 1);
                        int j0 = kb + 8 + (tj << 2);
                        float a[2][8], bb[4][8];
#pragma unroll
                        for (int r = 0; r < 2; r++) {
                            *(float4*)&a[r][0] = *(const float4*)&M[(i0 + r) * MS + kb];
                            *(float4*)&a[r][4] = *(const float4*)&M[(i0 + r) * MS + kb + 4];
                        }
#pragma unroll
                        for (int r = 0; r < 4; r++) {
                            *(float4*)&bb[r][0] = *(const float4*)&M[(j0 + r) * MS + kb];
                            *(float4*)&bb[r][4] = *(const float4*)&M[(j0 + r) * MS + kb + 4];
                        }
                        float acc[2][4];
#pragma unroll
                        for (int r = 0; r < 2; r++)
#pragma unroll
                            for (int q = 0; q < 4; q++) acc[r][q] = 0.f;
#pragma unroll
                        for (int c = 0; c < 8; c++)
#pragma unroll
                            for (int r = 0; r < 2; r++)
#pragma unroll
                                for (int q = 0; q < 4; q++)
                                    acc[r][q] += a[r][c] * bb[q][c];
#pragma unroll
                        for (int r = 0; r < 2; r++) {
                            float4 mv = *(const float4*)&M[(i0 + r) * MS + j0];
                            mv.x -= acc[r][0]; mv.y -= acc[r][1];
                            mv.z -= acc[r][2]; mv.w -= acc[r][3];
                            *(float4*)&M[(i0 + r) * MS + j0] = mv;
                        }
                    } else if (u < 2 * nMtG + 2 * nWt) {
                        int u2 = u - 2 * nMtG;
                        int t4 = u2 >> 1, half = u2 & 1;
                        int ti = t4 / wct, tj = t4 - ti * wct;
                        int i0 = kb + 8 + (ti << 2) + (half << 1);
                        int j0 = tj << 2;
                        float a[2][8], ws[8][4];
#pragma unroll
                        for (int r = 0; r < 2; r++) {
                            *(float4*)&a[r][0] = *(const float4*)&M[(i0 + r) * MS + kb];
                            *(float4*)&a[r][4] = *(const float4*)&M[(i0 + r) * MS + kb + 4];
                        }
#pragma unroll
                        for (int c = 0; c < 8; c++)
                            *(float4*)&ws[c][0] = *(const float4*)&W[(kb + c) * WS + j0];
                        float acc[2][4];
#pragma unroll
                        for (int r = 0; r < 2; r++)
#pragma unroll
                            for (int q = 0; q < 4; q++) acc[r][q] = 0.f;
#pragma unroll
                        for (int c = 0; c < 8; c++)
#pragma unroll
                            for (int r = 0; r < 2; r++)
#pragma unroll
                                for (int q = 0; q < 4; q++)
                                    acc[r][q] += a[r][c] * ws[c][q];
#pragma unroll
                        for (int r = 0; r < 2; r++) {
                            float4 wv = *(const float4*)&W[(i0 + r) * WS + j0];
                            wv.x -= acc[r][0]; wv.y -= acc[r][1];
                            wv.z -= acc[r][2]; wv.w -= acc[r][3];
                            *(float4*)&W[(i0 + r) * WS + j0] = wv;
                        }
                    } else {
                        int u3 = u - 2 * nMtG - 2 * nWt;
                        int i0 = kb + 8 + (u3 << 2);
                        float a[4][8], wc[8], av[4];
#pragma unroll
                        for (int r = 0; r < 4; r++) {
                            *(float4*)&a[r][0] = *(const float4*)&M[(i0 + r) * MS + kb];
                            *(float4*)&a[r][4] = *(const float4*)&M[(i0 + r) * MS + kb + 4];
                            av[r] = 0.f;
                        }
#pragma unroll
                        for (int c = 0; c < 8; c++) wc[c] = W[(kb + c) * WS + 64];
#pragma unroll
                        for (int c = 0; c < 8; c++)
#pragma unroll
                            for (int r = 0; r < 4; r++) av[r] += a[r][c] * wc[c];
#pragma unroll
                        for (int r = 0; r < 4; r++) W[(i0 + r) * WS + 64] -= av[r];
                    }
                }
            }
            __syncthreads();
        }
    }
}

// ---------------- lower-triangle SYRK: M(lower) = gAdd (+diag dd) - Z^T Z ----------------
__device__ __forceinline__ void syrk_lower(float* M, const float* W,
                                           const float* __restrict__ gAdd,
                                           const float* dd, int tid, bool tri) {
    if (tid < 136) {
        float xf = 8.f * (float)tid + 1.f;
        int ti = (int)((xf * rsqrtf(xf) - 1.f) * 0.5f);
        while ((ti + 1) * (ti + 2) / 2 <= tid) ++ti;
        while (ti * (ti + 1) / 2 > tid) --ti;
        int tj = tid - ((ti * (ti + 1)) >> 1);
        int i0 = ti << 2, j0 = tj << 2;
        float acc[4][4];
#pragma unroll
        for (int r = 0; r < 4; r++)
#pragma unroll
            for (int q = 0; q < 4; q++) acc[r][q] = 0.f;
        int k0 = tri ? i0 : 0;
#pragma unroll 4
        for (int k = k0; k < 64; k++) {
            const float* Wr = W + k * WS;
            float4 av = *(const float4*)&Wr[i0];
            float4 bv = *(const float4*)&Wr[j0];
            float a0 = av.x, a1 = av.y, a2 = av.z, a3 = av.w;
            float b0 = bv.x, b1 = bv.y, b2 = bv.z, b3 = bv.w;
            acc[0][0] += a0 * b0; acc[0][1] += a0 * b1; acc[0][2] += a0 * b2; acc[0][3] += a0 * b3;
            acc[1][0] += a1 * b0; acc[1][1] += a1 * b1; acc[1][2] += a1 * b2; acc[1][3] += a1 * b3;
            acc[2][0] += a2 * b0; acc[2][1] += a2 * b1; acc[2][2] += a2 * b2; acc[2][3] += a2 * b3;
            acc[3][0] += a3 * b0; acc[3][1] += a3 * b1; acc[3][2] += a3 * b2; acc[3][3] += a3 * b3;
        }
#pragma unroll
        for (int r = 0; r < 4; r++) {
            float4 g = *(const float4*)&gAdd[(i0 + r) * 64 + j0];
            float v[4] = { g.x - acc[r][0], g.y - acc[r][1], g.z - acc[r][2], g.w - acc[r][3] };
            if (dd && ti == tj) v[r] += dd[i0 + r];
            *(float4*)&M[(i0 + r) * MS + j0] = make_float4(v[0], v[1], v[2], v[3]);
        }
    }
}

// ---------------- transition phase (also used for the initial integral) ----------------
__device__ __forceinline__ void transition_phase(float* M, float* W, float* Li, float* mu,
                                                 const float* me, float* ldiag, float* idg,
                                                 float* sred, float* s_acc,
                                                 const float* tmu_s, int tid) {
    {   // W = Sab (float4 copy)
        int i = tid >> 2, q = tid & 3;
#pragma unroll
        for (int c = 0; c < 4; c++) {
            int jb = q * 16 + (c << 2);
            *(float4*)&W[i * WS + jb] = *(const float4*)&g_Sab[i * 64 + jb];
        }
    }
    if (tid < 64) W[tid * WS + 64] = me[tid] - tmu_s[tid];
    __syncthreads();
    chol64b<false>(M, W, Li, ldiag, idg, tid);
    if (tid >= 192) {
        int j = tid - 192;
        float z = W[j * WS + 64];
        sred[j] = 2.f * __logf(ldiag[j]) + z * z;
        float acc = 0.f;
#pragma unroll 4
        for (int k = 0; k < 64; k++) acc += W[k * WS + j] * W[k * WS + 64];
        mu[j] = tmu_s[64 + j] + acc;               // mu_t = mu_b + U^T z2
    }
    syrk_lower(M, W, g_Sbb, nullptr, tid, false);  // var_t = Sbb - U^T U
    __syncthreads();
    if (tid < 32) {
        float v = sred[tid] + sred[tid + 32];
#pragma unroll
        for (int o = 16; o; o >>= 1) v += __shfl_down_sync(0xffffffffu, v, o);
        if (tid == 0) *s_acc += -0.5f * (64.f * LOG2PI_F + v);
    }
}

// ---------------- the sequential scan: one persistent CTA ----------------
__global__ void __launch_bounds__(256, 1)
scan_kernel(const int* __restrict__ sentence, const int* __restrict__ slen_p, int slen_fb,
            const float* __restrict__ imu_emb, const float* __restrict__ icho_emb,
            const float* __restrict__ tmu) {
    __shared__ __align__(16) float M[64 * MS];
    __shared__ __align__(16) float W[64 * WS];
    __shared__ float Li[64];
    __shared__ float mu[64], me[64], mm[64], dd[64];
    __shared__ float ldiag[64], idg[64], sred[64], tmu_s[128];
    __shared__ float s_acc;

    int tid = threadIdx.x;
    int slen = slen_p ? slen_p[0] : slen_fb;

    // ---- init + prefetch token 0 ----
    float pmm = 0.f, pdd = 0.f;
    if (tid < 64 && slen > 0) {
        int tk = sentence[0];
        pmm = imu_emb[tk * 64 + tid];
        float c = icho_emb[tk * 64 + tid];
        pdd = c * c;
    }
    if (tid == 0) s_acc = 0.f;
    if (tid < 64) me[tid] = 0.f;
    if (tid < 128) tmu_s[tid] = tmu[tid];
    {
        int i = tid >> 2, q = tid & 3;
#pragma unroll
        for (int c = 0; c < 4; c++) {
            int jb = q * 16 + (c << 2);
            float4 v = *(const float4*)&g_Saa[i * 64 + jb];
            if (i >= jb && i < jb + 4) ((float*)&v)[i - jb] += 1.f;
            *(float4*)&M[i * MS + jb] = v;
        }
    }
    __syncthreads();
    transition_phase(M, W, Li, mu, me, ldiag, idg, sred, &s_acc, tmu_s, tid);  // (s0,m0,v0)

    // ---- sequential steps ----
    for (int t = 0; t < slen; t++) {
        // publish prefetched token t
        if (tid < 64) { mm[tid] = pmm; dd[tid] = pdd; }
        __syncthreads();
        // issue prefetch for token t+1 (hidden under this step's compute)
        if (tid < 64) {
            int nt = t + 1;
            if (nt < slen) {
                int tk = sentence[nt];
                pmm = imu_emb[tk * 64 + tid];
                float c = icho_emb[tk * 64 + tid];
                pdd = c * c;
            }
        }
        // -------- emission --------
        if (tid < 64) M[tid * MS + tid] += dd[tid];   // vs = var_prev + diag(d)
        {   // W = diag(d) in cols 0..63
            int i = tid >> 2, q = tid & 3;
#pragma unroll
            for (int c = 0; c < 4; c++) {
                int jb = q * 16 + (c << 2);
                float4 v = make_float4(0.f, 0.f, 0.f, 0.f);
                if (i >= jb && i < jb + 4) ((float*)&v)[i - jb] = dd[i];
                *(float4*)&W[i * WS + jb] = v;
            }
        }
        if (tid < 64) W[tid * WS + 64] = mu[tid] - mm[tid];
        __syncthreads();
        chol64b<true>(M, W, Li, ldiag, idg, tid);      // L(vs); Z = L^-1 diag(d); z
        if (tid >= 192) {
            int j = tid - 192;
            float z = W[j * WS + 64];
            sred[j] = 2.f * __logf(ldiag[j]) + z * z;
            float acc = 0.f;
#pragma unroll 4
            for (int k = j; k < 64; k++) acc += W[k * WS + j] * W[k * WS + 64];
            me[j] = mm[j] + acc;                       // mu_e = m + Z^T z
        }
        syrk_lower(M, W, g_Saa, dd, tid, true);        // lam = Saa + diag(d) - Z^T Z
        __syncthreads();
        if (tid < 32) {
            float v = sred[tid] + sred[tid + 32];
#pragma unroll
            for (int o = 16; o; o >>= 1) v += __shfl_down_sync(0xffffffffu, v, o);
            if (tid == 0) s_acc += -0.5f * (64.f * LOG2PI_F + v);
        }
        // -------- transition --------
        transition_phase(M, W, Li, mu, me, ldiag, idg, sred, &s_acc, tmu_s, tid);
    }

    // ---- publish carry ----
    if (tid < 64) g_fmu[tid] = mu[tid];
    for (int n = tid; n < 4096; n += 256) {
        int i = n >> 6, j = n & 63;
        if (j <= i) g_fvar[n] = M[i * MS + j];
    }
    if (tid == 0) g_fscore = s_acc;
}

// ---------------- decode: 50 independent small Choleskys ----------------
__global__ void decode_kernel(const float* __restrict__ omu, const float* __restrict__ ocho,
                              float* __restrict__ out) {
    __shared__ float M[64 * 65];
    __shared__ float b[64];
    __shared__ float ld[64];
    __shared__ float sred[64];
    int l = blockIdx.x, tid = threadIdx.x;  // 64 threads
    for (int n = tid; n < 4096; n += 64) {
        int i = n >> 6, j = n & 63;
        if (j <= i) {
            float v = g_fvar[n];
            if (i == j) { float c = ocho[l * 64 + i]; v += c * c; }
            M[i * 65 + j] = v;
        }
    }
    b[tid] = g_fmu[tid] - omu[l * 64 + tid];
    __syncthreads();
    for (int k = 0; k < 64; k++) {
        float rp = rsqrtf(M[k * 65 + k]);
        if (tid == 0) ld[k] = M[k * 65 + k] * rp;
        if (tid > k)       M[tid * 65 + k] *= rp;
        else if (tid == k) b[k] *= rp;
        __syncthreads();
        if (tid > k) {
            float c = M[tid * 65 + k];
            b[tid] -= c * b[k];
            for (int j = k + 1; j <= tid; j++) M[tid * 65 + j] -= c * M[j * 65 + k];
        }
        __syncthreads();
    }
    sred[tid] = 2.f * __logf(ld[tid]) + b[tid] * b[tid];
    __syncthreads();
    if (tid < 32) {
        float v = sred[tid] + sred[tid + 32];
#pragma unroll
        for (int o = 16; o; o >>= 1) v += __shfl_down_sync(0xffffffffu, v, o);
        if (tid == 0) out[l] = -0.5f * (64.f * LOG2PI_F + v) + g_fscore;
    }
}

// ---------------- launch ----------------
extern "C" void kernel_launch(void* const* d_in, const int* in_sizes, int n_in,
                              void* d_out, int out_size) {
    const int* sentence = (const int*)d_in[0];
    const int* slen_p   = nullptr;
    int base = 1;
    if (n_in >= 8) { slen_p = (const int*)d_in[1]; base = 2; }
    const float* imu  = (const float*)d_in[base + 0];
    const float* icho = (const float*)d_in[base + 1];
    const float* tmu  = (const float*)d_in[base + 2];
    const float* tcho = (const float*)d_in[base + 3];
    const float* omu  = (const float*)d_in[base + 4];
    const float* ocho = (const float*)d_in[base + 5];
    float* out = (float*)d_out;
    int slen_fb = in_sizes[0];

    prep_kernel<<<64, 256>>>(tcho);
    scan_kernel<<<1, 256>>>(sentence, slen_p, slen_fb, imu, icho, tmu);
    decode_kernel<<<out_size, 64>>>(omu, ocho, out);
}